// round 5
// baseline (speedup 1.0000x reference)
#include <cuda_runtime.h>
#include <cuda_bf16.h>
#include <math.h>

// Problem constants
#define BB   2
#define SS   2048
#define HH   1024
#define NH   16
#define HD   64
#define MM   (BB*SS)      // 4096
#define TOT  (MM*HH)      // 4194304

// Scratch (allocation-free rule: __device__ globals)
__device__ float g_Q[TOT];
__device__ float g_K[TOT];
__device__ float g_V[TOT];
__device__ float g_Ctx[TOT];
__device__ float g_X[TOT];

// ---------------------------------------------------------------------------
// GEMM: out[m,n] = sum_k A[m,k]*W[n,k] + bias[n]   (A: [4096,1024], W: [1024,1024])
// mode 0: write to QKV layout [b, h, s, d]
// mode 1: write linear + residual (for dense projection)
// Tile 128x128x16, 256 threads, 8x8 per-thread microtile.
// ---------------------------------------------------------------------------
__global__ void __launch_bounds__(256) gemm_bias_kernel(
    const float* __restrict__ A,
    const float* __restrict__ W,
    const float* __restrict__ bias,
    const float* __restrict__ resid,
    float* __restrict__ out,
    int mode)
{
    __shared__ float As[16][128];
    __shared__ float Bs[16][128];

    const int K = 1024;
    const int bm = blockIdx.y * 128;
    const int bn = blockIdx.x * 128;
    const int tid = threadIdx.x;
    const int tx = tid & 15;
    const int ty = tid >> 4;

    float acc[8][8];
#pragma unroll
    for (int i = 0; i < 8; i++)
#pragma unroll
        for (int j = 0; j < 8; j++) acc[i][j] = 0.f;

    for (int k0 = 0; k0 < K; k0 += 16) {
#pragma unroll
        for (int r = 0; r < 2; r++) {
            int f   = tid + r * 256;       // float4 id in [0,512)
            int row = f >> 2;
            int kc  = (f & 3) * 4;
            float4 va = *(const float4*)&A[(size_t)(bm + row) * K + k0 + kc];
            As[kc + 0][row] = va.x; As[kc + 1][row] = va.y;
            As[kc + 2][row] = va.z; As[kc + 3][row] = va.w;
            float4 vb = *(const float4*)&W[(size_t)(bn + row) * K + k0 + kc];
            Bs[kc + 0][row] = vb.x; Bs[kc + 1][row] = vb.y;
            Bs[kc + 2][row] = vb.z; Bs[kc + 3][row] = vb.w;
        }
        __syncthreads();
#pragma unroll
        for (int k = 0; k < 16; k++) {
            float a[8], b[8];
            *(float4*)&a[0] = *(const float4*)&As[k][ty * 4];
            *(float4*)&a[4] = *(const float4*)&As[k][64 + ty * 4];
            *(float4*)&b[0] = *(const float4*)&Bs[k][tx * 4];
            *(float4*)&b[4] = *(const float4*)&Bs[k][64 + tx * 4];
#pragma unroll
            for (int i = 0; i < 8; i++)
#pragma unroll
                for (int j = 0; j < 8; j++)
                    acc[i][j] += a[i] * b[j];
        }
        __syncthreads();
    }

#pragma unroll
    for (int i = 0; i < 8; i++) {
        int m = bm + ((i < 4) ? (ty * 4 + i) : (64 + ty * 4 + (i - 4)));
#pragma unroll
        for (int j = 0; j < 8; j++) {
            int n = bn + ((j < 4) ? (tx * 4 + j) : (64 + tx * 4 + (j - 4)));
            float v = acc[i][j] + bias[n];
            if (mode == 0) {
                int bb = m >> 11;      // batch
                int s  = m & 2047;
                int h  = n >> 6;
                int d  = n & 63;
                out[(((size_t)(bb * NH + h)) * SS + s) * HD + d] = v;
            } else {
                size_t idx = (size_t)m * HH + n;
                out[idx] = v + resid[idx];
            }
        }
    }
}

// ---------------------------------------------------------------------------
// Flash attention, fp32, hd=64, BM=BN=64, 256 threads (16x16, 4x4 microtile).
// Q/K/V in [b,h,s,d]; Ctx written in [b,s,h*64+d] (linear) for the dense GEMM.
// ---------------------------------------------------------------------------
__global__ void __launch_bounds__(256) flash_kernel(
    const float* __restrict__ Q,
    const float* __restrict__ Kin,
    const float* __restrict__ V,
    float* __restrict__ Ctx)
{
    extern __shared__ float smf[];
    float (*Qst)[68] = (float(*)[68])(smf);
    float (*Kst)[68] = (float(*)[68])(smf + 64 * 68);
    float (*Vs)[68]  = (float(*)[68])(smf + 2 * 64 * 68);
    float (*Ps)[68]  = (float(*)[68])(smf + 3 * 64 * 68);

    const int bh = blockIdx.y;   // b*16 + h, 0..31
    const int qt = blockIdx.x;   // 0..31 q-tiles of 64
    const int tid = threadIdx.x;
    const int tx = tid & 15;
    const int ty = tid >> 4;

    const float* Qb = Q   + (size_t)bh * SS * HD;
    const float* Kb = Kin + (size_t)bh * SS * HD;
    const float* Vb = V   + (size_t)bh * SS * HD;

    // Load Q tile (64 rows x 64 d) transposed -> Qst[d][q]
#pragma unroll
    for (int r = 0; r < 4; r++) {
        int f  = tid + r * 256;     // float4 id in [0,1024)
        int q  = f >> 4;
        int d4 = (f & 15) * 4;
        float4 v = *(const float4*)&Qb[(size_t)(qt * 64 + q) * HD + d4];
        Qst[d4 + 0][q] = v.x; Qst[d4 + 1][q] = v.y;
        Qst[d4 + 2][q] = v.z; Qst[d4 + 3][q] = v.w;
    }

    float m_i[4], l_i[4], acc[4][4];
#pragma unroll
    for (int i = 0; i < 4; i++) {
        m_i[i] = -1e30f; l_i[i] = 0.f;
#pragma unroll
        for (int j = 0; j < 4; j++) acc[i][j] = 0.f;
    }

    for (int kt = 0; kt < SS / 64; kt++) {
        __syncthreads();   // protect Kst/Vs/Ps reuse across iterations
#pragma unroll
        for (int r = 0; r < 4; r++) {
            int f  = tid + r * 256;
            int kk = f >> 4;
            int d4 = (f & 15) * 4;
            float4 v = *(const float4*)&Kb[(size_t)(kt * 64 + kk) * HD + d4];
            Kst[d4 + 0][kk] = v.x; Kst[d4 + 1][kk] = v.y;
            Kst[d4 + 2][kk] = v.z; Kst[d4 + 3][kk] = v.w;
            float4 w = *(const float4*)&Vb[(size_t)(kt * 64 + kk) * HD + d4];
            *(float4*)&Vs[kk][d4] = w;
        }
        __syncthreads();

        // Scores S = (Q K^T) * 1/sqrt(64)
        float s[4][4];
#pragma unroll
        for (int i = 0; i < 4; i++)
#pragma unroll
            for (int j = 0; j < 4; j++) s[i][j] = 0.f;
#pragma unroll
        for (int d = 0; d < 64; d++) {
            float a[4], b[4];
            *(float4*)a = *(const float4*)&Qst[d][ty * 4];
            *(float4*)b = *(const float4*)&Kst[d][tx * 4];
#pragma unroll
            for (int i = 0; i < 4; i++)
#pragma unroll
                for (int j = 0; j < 4; j++)
                    s[i][j] += a[i] * b[j];
        }

        // Online softmax (row groups = 16 lanes sharing ty)
#pragma unroll
        for (int i = 0; i < 4; i++) {
#pragma unroll
            for (int j = 0; j < 4; j++) s[i][j] *= 0.125f;
            float mx = fmaxf(fmaxf(s[i][0], s[i][1]), fmaxf(s[i][2], s[i][3]));
#pragma unroll
            for (int o = 8; o >= 1; o >>= 1)
                mx = fmaxf(mx, __shfl_xor_sync(0xffffffffu, mx, o, 16));
            float mnew = fmaxf(m_i[i], mx);
            float alpha = __expf(m_i[i] - mnew);
            float rsum = 0.f;
#pragma unroll
            for (int j = 0; j < 4; j++) {
                s[i][j] = __expf(s[i][j] - mnew);
                rsum += s[i][j];
            }
#pragma unroll
            for (int o = 8; o >= 1; o >>= 1)
                rsum += __shfl_xor_sync(0xffffffffu, rsum, o, 16);
            l_i[i] = l_i[i] * alpha + rsum;
            m_i[i] = mnew;
#pragma unroll
            for (int j = 0; j < 4; j++) acc[i][j] *= alpha;
            // store P transposed: Ps[k][q]
#pragma unroll
            for (int j = 0; j < 4; j++)
                Ps[tx * 4 + j][ty * 4 + i] = s[i][j];
        }
        __syncthreads();

        // acc += P V
#pragma unroll
        for (int kk = 0; kk < 64; kk++) {
            float a[4], b[4];
            *(float4*)a = *(const float4*)&Ps[kk][ty * 4];
            *(float4*)b = *(const float4*)&Vs[kk][tx * 4];
#pragma unroll
            for (int i = 0; i < 4; i++)
#pragma unroll
                for (int j = 0; j < 4; j++)
                    acc[i][j] += a[i] * b[j];
        }
    }

    // Write ctx in [b, s, h*64+d]
    const int b = bh >> 4;
    const int h = bh & 15;
#pragma unroll
    for (int i = 0; i < 4; i++) {
        int qg = qt * 64 + ty * 4 + i;
        float inv = 1.f / l_i[i];
#pragma unroll
        for (int j = 0; j < 4; j++) {
            int d = tx * 4 + j;
            Ctx[((size_t)(b * SS + qg)) * HH + h * HD + d] = acc[i][j] * inv;
        }
    }
}

// ---------------------------------------------------------------------------
// LayerNorm over last dim (1024), one 256-thread block per row.
// ---------------------------------------------------------------------------
__device__ __forceinline__ float block_sum(float v) {
    __shared__ float red[8];
    __syncthreads();  // safe reuse of red across calls
#pragma unroll
    for (int o = 16; o >= 1; o >>= 1)
        v += __shfl_xor_sync(0xffffffffu, v, o);
    int w = threadIdx.x >> 5;
    if ((threadIdx.x & 31) == 0) red[w] = v;
    __syncthreads();
    if (w == 0) {
        float t = (threadIdx.x < 8) ? red[threadIdx.x] : 0.f;
#pragma unroll
        for (int o = 4; o >= 1; o >>= 1)
            t += __shfl_xor_sync(0xffffffffu, t, o);
        if (threadIdx.x == 0) red[0] = t;
    }
    __syncthreads();
    return red[0];
}

__global__ void __launch_bounds__(256) ln_kernel(
    const float* __restrict__ X,
    const float* __restrict__ gamma,
    const float* __restrict__ beta,
    float* __restrict__ out)
{
    const int row = blockIdx.x;
    const int tid = threadIdx.x;
    const float* x = X + (size_t)row * HH;

    float4 v = *(const float4*)&x[tid * 4];
    float s = v.x + v.y + v.z + v.w;
    float mean = block_sum(s) * (1.f / HH);
    float dx = v.x - mean, dy = v.y - mean, dz = v.z - mean, dw = v.w - mean;
    float vs = dx * dx + dy * dy + dz * dz + dw * dw;
    float var = block_sum(vs) * (1.f / HH);
    float inv = rsqrtf(var + 1e-5f);

    float4 g  = *(const float4*)&gamma[tid * 4];
    float4 bt = *(const float4*)&beta[tid * 4];
    float4 o;
    o.x = dx * inv * g.x + bt.x;
    o.y = dy * inv * g.y + bt.y;
    o.z = dz * inv * g.z + bt.z;
    o.w = dw * inv * g.w + bt.w;
    *(float4*)&out[(size_t)row * HH + tid * 4] = o;
}

// ---------------------------------------------------------------------------
extern "C" void kernel_launch(void* const* d_in, const int* in_sizes, int n_in,
                              void* d_out, int out_size)
{
    const float* hidden = (const float*)d_in[0];
    const float* Wq = (const float*)d_in[1];  const float* bq = (const float*)d_in[2];
    const float* Wk = (const float*)d_in[3];  const float* bk = (const float*)d_in[4];
    const float* Wv = (const float*)d_in[5];  const float* bv = (const float*)d_in[6];
    const float* Wd = (const float*)d_in[7];  const float* bd = (const float*)d_in[8];
    const float* gamma = (const float*)d_in[9];
    const float* beta  = (const float*)d_in[10];
    float* out = (float*)d_out;

    float *Qp, *Kp, *Vp, *Cp, *Xp;
    cudaGetSymbolAddress((void**)&Qp, g_Q);
    cudaGetSymbolAddress((void**)&Kp, g_K);
    cudaGetSymbolAddress((void**)&Vp, g_V);
    cudaGetSymbolAddress((void**)&Cp, g_Ctx);
    cudaGetSymbolAddress((void**)&Xp, g_X);

    const int flash_smem = 4 * 64 * 68 * (int)sizeof(float);  // 69632 B
    cudaFuncSetAttribute(flash_kernel,
                         cudaFuncAttributeMaxDynamicSharedMemorySize, flash_smem);

    dim3 ggrid(HH / 128, MM / 128);   // (8, 32)
    gemm_bias_kernel<<<ggrid, 256>>>(hidden, Wq, bq, nullptr, Qp, 0);
    gemm_bias_kernel<<<ggrid, 256>>>(hidden, Wk, bk, nullptr, Kp, 0);
    gemm_bias_kernel<<<ggrid, 256>>>(hidden, Wv, bv, nullptr, Vp, 0);

    flash_kernel<<<dim3(SS / 64, BB * NH), 256, flash_smem>>>(Qp, Kp, Vp, Cp);

    gemm_bias_kernel<<<ggrid, 256>>>(Cp, Wd, bd, hidden, Xp, 1);

    ln_kernel<<<MM, 256>>>(Xp, gamma, beta, out);
}

// round 7
// speedup vs baseline: 4.9322x; 4.9322x over previous
#include <cuda_runtime.h>
#include <cuda_bf16.h>
#include <math.h>

// Problem constants
#define BB   2
#define SS   2048
#define HH   1024
#define NH   16
#define HD   64
#define MM   (BB*SS)      // 4096
#define TOT  (MM*HH)      // 4194304

// Scratch (allocation-free rule: __device__ globals)
__device__ __nv_bfloat16 g_Qb[TOT];
__device__ __nv_bfloat16 g_Kb[TOT];
__device__ __nv_bfloat16 g_Vb[TOT];
__device__ __nv_bfloat16 g_Cb[TOT];
__device__ float g_X[TOT];

// ---------------------------------------------------------------------------
// MMA / ldmatrix helpers (sm_80+ warp-level, valid on sm_103a)
// ---------------------------------------------------------------------------
__device__ __forceinline__ unsigned smem_u32(const void* p) {
    return (unsigned)__cvta_generic_to_shared(p);
}
__device__ __forceinline__ void ldsm4(unsigned* r, unsigned a) {
    asm volatile("ldmatrix.sync.aligned.m8n8.x4.shared.b16 {%0,%1,%2,%3}, [%4];"
        : "=r"(r[0]), "=r"(r[1]), "=r"(r[2]), "=r"(r[3]) : "r"(a));
}
__device__ __forceinline__ void ldsm4t(unsigned* r, unsigned a) {
    asm volatile("ldmatrix.sync.aligned.m8n8.x4.trans.shared.b16 {%0,%1,%2,%3}, [%4];"
        : "=r"(r[0]), "=r"(r[1]), "=r"(r[2]), "=r"(r[3]) : "r"(a));
}
__device__ __forceinline__ void mma_bf16(float* c, const unsigned* a, const unsigned* b) {
    asm volatile(
        "mma.sync.aligned.m16n8k16.row.col.f32.bf16.bf16.f32 "
        "{%0,%1,%2,%3}, {%4,%5,%6,%7}, {%8,%9}, {%0,%1,%2,%3};"
        : "+f"(c[0]), "+f"(c[1]), "+f"(c[2]), "+f"(c[3])
        : "r"(a[0]), "r"(a[1]), "r"(a[2]), "r"(a[3]), "r"(b[0]), "r"(b[1]));
}
// pack two floats -> bf16x2 (RNA). PTX cvt.bf16x2: first src -> upper half.
__device__ __forceinline__ unsigned packbf(float lo, float hi) {
    unsigned d;
    asm("cvt.rn.bf16x2.f32 %0, %1, %2;" : "=r"(d) : "f"(hi), "f"(lo));
    return d;
}

// ---------------------------------------------------------------------------
// Tensor-core GEMM: out[m,n] = sum_k A[m,k]*W[n,k] + bias[n]
// ABF16: A input is bf16 (ctx) vs fp32 (hidden).
// OMODE 0: bf16 scatter to [b,h,s,d].  OMODE 1: fp32 linear + residual.
// Block tile 128x128x32, 8 warps (2M x 4N), warp tile 64x32, double-buffered.
// ---------------------------------------------------------------------------
template<int ABF16, int OMODE>
__global__ void __launch_bounds__(256) gemm_mma(
    const void* __restrict__ Ain,
    const float* __restrict__ W,
    const float* __restrict__ bias,
    const float* __restrict__ resid,
    void* __restrict__ outp)
{
    __shared__ __nv_bfloat16 As[2][128 * 40];   // 32 k + pad->40 (bank-clean LDSM)
    __shared__ __nv_bfloat16 Bs[2][128 * 40];
    const int K = 1024;
    const int tid = threadIdx.x;
    const int lane = tid & 31;
    const int warp = tid >> 5;
    const int wm = warp & 1, wn = warp >> 1;
    const int bm = blockIdx.y * 128, bn = blockIdx.x * 128;
    const int srow = tid >> 1, sseg = (tid & 1) * 16;

    const float* Af = (const float*)Ain;
    const __nv_bfloat16* Ab = (const __nv_bfloat16*)Ain;

    float acc[4][4][4];
#pragma unroll
    for (int i = 0; i < 4; i++)
#pragma unroll
        for (int j = 0; j < 4; j++)
#pragma unroll
            for (int k = 0; k < 4; k++) acc[i][j][k] = 0.f;

    float4 fa[4], fb[4];
    uint4 ua[2];

    auto gload = [&](int k0) {
        if (ABF16) {
            const uint4* p = (const uint4*)(Ab + (size_t)(bm + srow) * K + k0 + sseg);
            ua[0] = p[0]; ua[1] = p[1];
        } else {
#pragma unroll
            for (int i = 0; i < 4; i++)
                fa[i] = *(const float4*)(Af + (size_t)(bm + srow) * K + k0 + sseg + i * 4);
        }
#pragma unroll
        for (int i = 0; i < 4; i++)
            fb[i] = *(const float4*)(W + (size_t)(bn + srow) * K + k0 + sseg + i * 4);
    };
    auto sstore = [&](int buf) {
        __nv_bfloat16* da = &As[buf][srow * 40 + sseg];
        if (ABF16) {
            ((uint4*)da)[0] = ua[0]; ((uint4*)da)[1] = ua[1];
        } else {
            uint4 u0 = make_uint4(packbf(fa[0].x, fa[0].y), packbf(fa[0].z, fa[0].w),
                                  packbf(fa[1].x, fa[1].y), packbf(fa[1].z, fa[1].w));
            uint4 u1 = make_uint4(packbf(fa[2].x, fa[2].y), packbf(fa[2].z, fa[2].w),
                                  packbf(fa[3].x, fa[3].y), packbf(fa[3].z, fa[3].w));
            ((uint4*)da)[0] = u0; ((uint4*)da)[1] = u1;
        }
        __nv_bfloat16* db = &Bs[buf][srow * 40 + sseg];
        uint4 v0 = make_uint4(packbf(fb[0].x, fb[0].y), packbf(fb[0].z, fb[0].w),
                              packbf(fb[1].x, fb[1].y), packbf(fb[1].z, fb[1].w));
        uint4 v1 = make_uint4(packbf(fb[2].x, fb[2].y), packbf(fb[2].z, fb[2].w),
                              packbf(fb[3].x, fb[3].y), packbf(fb[3].z, fb[3].w));
        ((uint4*)db)[0] = v0; ((uint4*)db)[1] = v1;
    };

    gload(0);
    sstore(0);
    __syncthreads();

    for (int t = 0; t < 32; t++) {
        if (t < 31) gload((t + 1) * 32);
        const int buf = t & 1;
        unsigned smA = smem_u32(&As[buf][0]);
        unsigned smB = smem_u32(&Bs[buf][0]);
#pragma unroll
        for (int kk = 0; kk < 2; kk++) {
            unsigned a[4][4], b[4][2];
#pragma unroll
            for (int mt = 0; mt < 4; mt++) {
                int row = wm * 64 + mt * 16 + (lane & 15);
                int col = kk * 16 + (lane >> 4) * 8;
                ldsm4(a[mt], smA + (unsigned)(row * 40 + col) * 2u);
            }
#pragma unroll
            for (int np = 0; np < 2; np++) {
                int row = wn * 32 + np * 16 + (lane & 7) + ((lane >> 4) << 3);
                int col = kk * 16 + ((lane >> 3) & 1) * 8;
                unsigned r[4];
                ldsm4(r, smB + (unsigned)(row * 40 + col) * 2u);
                b[np * 2][0] = r[0];     b[np * 2][1] = r[1];
                b[np * 2 + 1][0] = r[2]; b[np * 2 + 1][1] = r[3];
            }
#pragma unroll
            for (int mt = 0; mt < 4; mt++)
#pragma unroll
                for (int nt = 0; nt < 4; nt++)
                    mma_bf16(acc[mt][nt], a[mt], b[nt]);
        }
        if (t < 31) sstore(buf ^ 1);
        __syncthreads();
    }

    // Epilogue. c-frag: c0,c1 = (row=lane>>2, col=2*(lane&3)+{0,1}); c2,c3 = row+8.
#pragma unroll
    for (int mt = 0; mt < 4; mt++) {
        int r0 = bm + wm * 64 + mt * 16 + (lane >> 2);
#pragma unroll
        for (int nt = 0; nt < 4; nt++) {
            int c = bn + wn * 32 + nt * 8 + 2 * (lane & 3);
            float b0 = bias[c], b1 = bias[c + 1];
            float v00 = acc[mt][nt][0] + b0, v01 = acc[mt][nt][1] + b1;
            float v10 = acc[mt][nt][2] + b0, v11 = acc[mt][nt][3] + b1;
            if (OMODE == 0) {
                __nv_bfloat16* O = (__nv_bfloat16*)outp;
                int h = c >> 6, d = c & 63;
                {
                    int bi = r0 >> 11, s = r0 & 2047;
                    size_t idx = ((size_t)((bi * NH + h) * SS + s)) * HD + d;
                    *(__nv_bfloat162*)(O + idx) = __floats2bfloat162_rn(v00, v01);
                }
                {
                    int r1 = r0 + 8;
                    int bi = r1 >> 11, s = r1 & 2047;
                    size_t idx = ((size_t)((bi * NH + h) * SS + s)) * HD + d;
                    *(__nv_bfloat162*)(O + idx) = __floats2bfloat162_rn(v10, v11);
                }
            } else {
                float* O = (float*)outp;
                size_t i0 = (size_t)r0 * HH + c;
                size_t i1 = (size_t)(r0 + 8) * HH + c;
                *(float2*)(O + i0) = make_float2(v00 + resid[i0], v01 + resid[i0 + 1]);
                *(float2*)(O + i1) = make_float2(v10 + resid[i1], v11 + resid[i1 + 1]);
            }
        }
    }
}

// ---------------------------------------------------------------------------
// Flash attention, bf16 tensor cores. Q-tile 128 rows, K-tiles of 64.
// 8 warps x 16 q-rows; each warp owns full 64-key width -> softmax in-quad.
// FA2 trick: score C-fragments convert in-register to P A-fragments.
// ---------------------------------------------------------------------------
__global__ void __launch_bounds__(256) flash_mma(
    const __nv_bfloat16* __restrict__ Q,
    const __nv_bfloat16* __restrict__ Kin,
    const __nv_bfloat16* __restrict__ V,
    __nv_bfloat16* __restrict__ Ctx)
{
    __shared__ __nv_bfloat16 Qs[128 * 72];   // stride 72 halfs: LDSM conflict-free
    __shared__ __nv_bfloat16 Ks[64 * 72];
    __shared__ __nv_bfloat16 Vs[64 * 72];
    const int tid = threadIdx.x, lane = tid & 31, warp = tid >> 5;
    const int bh = blockIdx.y, qt = blockIdx.x;
    const size_t base = (size_t)bh * SS * HD;

    // Stage Q tile (128 x 64 bf16)
    {
        int row = tid >> 1, seg = (tid & 1) * 32;
        const uint4* s = (const uint4*)(Q + base + (size_t)(qt * 128 + row) * HD + seg);
        uint4* d = (uint4*)(Qs + row * 72 + seg);
        d[0] = s[0]; d[1] = s[1]; d[2] = s[2]; d[3] = s[3];
    }
    __syncthreads();

    // Hoist Q fragments for all 4 d-ksteps (stay in regs for whole kernel)
    unsigned qa[4][4];
    {
        unsigned smQ = smem_u32(Qs);
        int row = warp * 16 + (lane & 15);
#pragma unroll
        for (int ks = 0; ks < 4; ks++) {
            int col = ks * 16 + (lane >> 4) * 8;
            ldsm4(qa[ks], smQ + (unsigned)(row * 72 + col) * 2u);
        }
    }

    float ctx[8][4];
#pragma unroll
    for (int o = 0; o < 8; o++)
#pragma unroll
        for (int j = 0; j < 4; j++) ctx[o][j] = 0.f;
    float m0 = -1e30f, m1 = -1e30f, l0 = 0.f, l1 = 0.f;
    const float C = 0.18033688011112042f;   // log2(e)/sqrt(64)

    unsigned smK = smem_u32(Ks), smV = smem_u32(Vs);
    const int krow = tid >> 2, kseg = (tid & 3) * 16;

    for (int kt = 0; kt < SS / 64; kt++) {
        __syncthreads();
        {
            size_t g = base + (size_t)(kt * 64 + krow) * HD + kseg;
            const uint4* sk = (const uint4*)(Kin + g);
            uint4* dk = (uint4*)(Ks + krow * 72 + kseg);
            dk[0] = sk[0]; dk[1] = sk[1];
            const uint4* sv = (const uint4*)(V + g);
            uint4* dv = (uint4*)(Vs + krow * 72 + kseg);
            dv[0] = sv[0]; dv[1] = sv[1];
        }
        __syncthreads();

        // S = Q K^T  (raw, scale folded into exp)
        float s[8][4];
#pragma unroll
        for (int o = 0; o < 8; o++)
#pragma unroll
            for (int j = 0; j < 4; j++) s[o][j] = 0.f;
#pragma unroll
        for (int ks = 0; ks < 4; ks++) {
            unsigned kb[8][2];
#pragma unroll
            for (int np = 0; np < 4; np++) {
                int row = np * 16 + (lane & 7) + ((lane >> 4) << 3);
                int col = ks * 16 + ((lane >> 3) & 1) * 8;
                unsigned r[4];
                ldsm4(r, smK + (unsigned)(row * 72 + col) * 2u);
                kb[np * 2][0] = r[0];     kb[np * 2][1] = r[1];
                kb[np * 2 + 1][0] = r[2]; kb[np * 2 + 1][1] = r[3];
            }
#pragma unroll
            for (int o = 0; o < 8; o++)
                mma_bf16(s[o], qa[ks], kb[o]);
        }

        // Online softmax: rows r=lane>>2 (c0,c1) and r+8 (c2,c3); quad shuffles.
        float mx0 = s[0][0], mx1 = s[0][2];
#pragma unroll
        for (int o = 0; o < 8; o++) {
            mx0 = fmaxf(mx0, fmaxf(s[o][0], s[o][1]));
            mx1 = fmaxf(mx1, fmaxf(s[o][2], s[o][3]));
        }
        mx0 = fmaxf(mx0, __shfl_xor_sync(0xffffffffu, mx0, 1));
        mx0 = fmaxf(mx0, __shfl_xor_sync(0xffffffffu, mx0, 2));
        mx1 = fmaxf(mx1, __shfl_xor_sync(0xffffffffu, mx1, 1));
        mx1 = fmaxf(mx1, __shfl_xor_sync(0xffffffffu, mx1, 2));
        float mn0 = fmaxf(m0, mx0), mn1 = fmaxf(m1, mx1);
        float a0 = exp2f((m0 - mn0) * C), a1 = exp2f((m1 - mn1) * C);
        float sum0 = 0.f, sum1 = 0.f;
#pragma unroll
        for (int o = 0; o < 8; o++) {
            s[o][0] = exp2f((s[o][0] - mn0) * C);
            s[o][1] = exp2f((s[o][1] - mn0) * C);
            s[o][2] = exp2f((s[o][2] - mn1) * C);
            s[o][3] = exp2f((s[o][3] - mn1) * C);
            sum0 += s[o][0] + s[o][1];
            sum1 += s[o][2] + s[o][3];
        }
        sum0 += __shfl_xor_sync(0xffffffffu, sum0, 1);
        sum0 += __shfl_xor_sync(0xffffffffu, sum0, 2);
        sum1 += __shfl_xor_sync(0xffffffffu, sum1, 1);
        sum1 += __shfl_xor_sync(0xffffffffu, sum1, 2);
        l0 = l0 * a0 + sum0; l1 = l1 * a1 + sum1;
        m0 = mn0; m1 = mn1;
#pragma unroll
        for (int o = 0; o < 8; o++) {
            ctx[o][0] *= a0; ctx[o][1] *= a0;
            ctx[o][2] *= a1; ctx[o][3] *= a1;
        }

        // ctx += P @ V   (P from score frags, V via ldmatrix.trans)
#pragma unroll
        for (int ks = 0; ks < 4; ks++) {
            unsigned pa[4] = {
                packbf(s[2 * ks][0],     s[2 * ks][1]),
                packbf(s[2 * ks][2],     s[2 * ks][3]),
                packbf(s[2 * ks + 1][0], s[2 * ks + 1][1]),
                packbf(s[2 * ks + 1][2], s[2 * ks + 1][3])
            };
            unsigned vb[8][2];
#pragma unroll
            for (int dp = 0; dp < 4; dp++) {
                int row = ks * 16 + (lane & 7) + (((lane >> 3) & 1) << 3);
                int col = (dp * 2 + (lane >> 4)) * 8;
                unsigned r[4];
                ldsm4t(r, smV + (unsigned)(row * 72 + col) * 2u);
                vb[dp * 2][0] = r[0];     vb[dp * 2][1] = r[1];
                vb[dp * 2 + 1][0] = r[2]; vb[dp * 2 + 1][1] = r[3];
            }
#pragma unroll
            for (int o = 0; o < 8; o++)
                mma_bf16(ctx[o], pa, vb[o]);
        }
    }

    // Epilogue: normalize, write ctx bf16 in [b, s, h*64+d]
    float inv0 = 1.f / l0, inv1 = 1.f / l1;
    int b = bh >> 4, h = bh & 15;
    int r0 = qt * 128 + warp * 16 + (lane >> 2);
    int r1 = r0 + 8;
#pragma unroll
    for (int o = 0; o < 8; o++) {
        int d = o * 8 + 2 * (lane & 3);
        size_t i0 = ((size_t)(b * SS + r0)) * HH + h * HD + d;
        size_t i1 = ((size_t)(b * SS + r1)) * HH + h * HD + d;
        *(__nv_bfloat162*)(Ctx + i0) = __floats2bfloat162_rn(ctx[o][0] * inv0, ctx[o][1] * inv0);
        *(__nv_bfloat162*)(Ctx + i1) = __floats2bfloat162_rn(ctx[o][2] * inv1, ctx[o][3] * inv1);
    }
}

// ---------------------------------------------------------------------------
// LayerNorm over last dim (1024), one 256-thread block per row. (fp32)
// ---------------------------------------------------------------------------
__device__ __forceinline__ float block_sum(float v) {
    __shared__ float red[8];
    __syncthreads();
#pragma unroll
    for (int o = 16; o >= 1; o >>= 1)
        v += __shfl_xor_sync(0xffffffffu, v, o);
    int w = threadIdx.x >> 5;
    if ((threadIdx.x & 31) == 0) red[w] = v;
    __syncthreads();
    if (w == 0) {
        float t = (threadIdx.x < 8) ? red[threadIdx.x] : 0.f;
#pragma unroll
        for (int o = 4; o >= 1; o >>= 1)
            t += __shfl_xor_sync(0xffffffffu, t, o);
        if (threadIdx.x == 0) red[0] = t;
    }
    __syncthreads();
    return red[0];
}

__global__ void __launch_bounds__(256) ln_kernel(
    const float* __restrict__ X,
    const float* __restrict__ gamma,
    const float* __restrict__ beta,
    float* __restrict__ out)
{
    const int row = blockIdx.x;
    const int tid = threadIdx.x;
    const float* x = X + (size_t)row * HH;

    float4 v = *(const float4*)&x[tid * 4];
    float s = v.x + v.y + v.z + v.w;
    float mean = block_sum(s) * (1.f / HH);
    float dx = v.x - mean, dy = v.y - mean, dz = v.z - mean, dw = v.w - mean;
    float vs = dx * dx + dy * dy + dz * dz + dw * dw;
    float var = block_sum(vs) * (1.f / HH);
    float inv = rsqrtf(var + 1e-5f);

    float4 g  = *(const float4*)&gamma[tid * 4];
    float4 bt = *(const float4*)&beta[tid * 4];
    float4 o;
    o.x = dx * inv * g.x + bt.x;
    o.y = dy * inv * g.y + bt.y;
    o.z = dz * inv * g.z + bt.z;
    o.w = dw * inv * g.w + bt.w;
    *(float4*)&out[(size_t)row * HH + tid * 4] = o;
}

// ---------------------------------------------------------------------------
extern "C" void kernel_launch(void* const* d_in, const int* in_sizes, int n_in,
                              void* d_out, int out_size)
{
    const float* hidden = (const float*)d_in[0];
    const float* Wq = (const float*)d_in[1];  const float* bq = (const float*)d_in[2];
    const float* Wk = (const float*)d_in[3];  const float* bk = (const float*)d_in[4];
    const float* Wv = (const float*)d_in[5];  const float* bv = (const float*)d_in[6];
    const float* Wd = (const float*)d_in[7];  const float* bd = (const float*)d_in[8];
    const float* gamma = (const float*)d_in[9];
    const float* beta  = (const float*)d_in[10];
    float* out = (float*)d_out;

    __nv_bfloat16 *Qp, *Kp, *Vp, *Cp;
    float* Xp;
    cudaGetSymbolAddress((void**)&Qp, g_Qb);
    cudaGetSymbolAddress((void**)&Kp, g_Kb);
    cudaGetSymbolAddress((void**)&Vp, g_Vb);
    cudaGetSymbolAddress((void**)&Cp, g_Cb);
    cudaGetSymbolAddress((void**)&Xp, g_X);

    dim3 ggrid(HH / 128, MM / 128);   // (8, 32)
    gemm_mma<0, 0><<<ggrid, 256>>>(hidden, Wq, bq, nullptr, Qp);
    gemm_mma<0, 0><<<ggrid, 256>>>(hidden, Wk, bk, nullptr, Kp);
    gemm_mma<0, 0><<<ggrid, 256>>>(hidden, Wv, bv, nullptr, Vp);

    flash_mma<<<dim3(SS / 128, BB * NH), 256>>>(Qp, Kp, Vp, Cp);

    gemm_mma<1, 1><<<ggrid, 256>>>(Cp, Wd, bd, hidden, Xp);

    ln_kernel<<<MM, 256>>>(Xp, gamma, beta, out);
}

// round 8
// speedup vs baseline: 6.5073x; 1.3193x over previous
#include <cuda_runtime.h>
#include <cuda_bf16.h>
#include <math.h>

// Problem constants
#define BB   2
#define SS   2048
#define HH   1024
#define NH   16
#define HD   64
#define MM   (BB*SS)      // 4096
#define TOT  (MM*HH)      // 4194304

// Scratch (allocation-free rule: __device__ globals)
__device__ __nv_bfloat16 g_Hb[TOT];            // hidden in bf16
__device__ __nv_bfloat16 g_Wqkv[3 * HH * HH];  // packed Wq|Wk|Wv bf16
__device__ __nv_bfloat16 g_Wdb[HH * HH];       // Wd bf16
__device__ float         g_bqkv[3 * HH];       // packed bias
__device__ __nv_bfloat16 g_Qb[TOT];
__device__ __nv_bfloat16 g_Kb[TOT];
__device__ __nv_bfloat16 g_Vb[TOT];
__device__ __nv_bfloat16 g_Cb[TOT];
__device__ float g_X[TOT];

// ---------------------------------------------------------------------------
// Helpers
// ---------------------------------------------------------------------------
__device__ __forceinline__ unsigned smem_u32(const void* p) {
    return (unsigned)__cvta_generic_to_shared(p);
}
__device__ __forceinline__ void ldsm4(unsigned* r, unsigned a) {
    asm volatile("ldmatrix.sync.aligned.m8n8.x4.shared.b16 {%0,%1,%2,%3}, [%4];"
        : "=r"(r[0]), "=r"(r[1]), "=r"(r[2]), "=r"(r[3]) : "r"(a));
}
__device__ __forceinline__ void ldsm4t(unsigned* r, unsigned a) {
    asm volatile("ldmatrix.sync.aligned.m8n8.x4.trans.shared.b16 {%0,%1,%2,%3}, [%4];"
        : "=r"(r[0]), "=r"(r[1]), "=r"(r[2]), "=r"(r[3]) : "r"(a));
}
__device__ __forceinline__ void mma_bf16(float* c, const unsigned* a, const unsigned* b) {
    asm volatile(
        "mma.sync.aligned.m16n8k16.row.col.f32.bf16.bf16.f32 "
        "{%0,%1,%2,%3}, {%4,%5,%6,%7}, {%8,%9}, {%0,%1,%2,%3};"
        : "+f"(c[0]), "+f"(c[1]), "+f"(c[2]), "+f"(c[3])
        : "r"(a[0]), "r"(a[1]), "r"(a[2]), "r"(a[3]), "r"(b[0]), "r"(b[1]));
}
__device__ __forceinline__ unsigned packbf(float lo, float hi) {
    unsigned d;
    asm("cvt.rn.bf16x2.f32 %0, %1, %2;" : "=r"(d) : "f"(hi), "f"(lo));
    return d;
}
#define CP_ASYNC16(dst, src) \
    asm volatile("cp.async.cg.shared.global [%0], [%1], 16;" :: "r"(dst), "l"(src))
#define CP_COMMIT()  asm volatile("cp.async.commit_group;")
#define CP_WAIT1()   asm volatile("cp.async.wait_group 1;")

// ---------------------------------------------------------------------------
// Convert/pack pass: hidden -> bf16, Wq|Wk|Wv -> packed bf16, Wd -> bf16,
// bq|bk|bv -> packed fp32. One float4 per thread, grid 8192 x 256.
// ---------------------------------------------------------------------------
__global__ void __launch_bounds__(256) convert_kernel(
    const float* __restrict__ hidden,
    const float* __restrict__ Wq, const float* __restrict__ Wk,
    const float* __restrict__ Wv, const float* __restrict__ Wd,
    const float* __restrict__ bq, const float* __restrict__ bk,
    const float* __restrict__ bv,
    __nv_bfloat16* __restrict__ Hb, __nv_bfloat16* __restrict__ Wqkv,
    __nv_bfloat16* __restrict__ Wdb, float* __restrict__ bqkv)
{
    int gid = blockIdx.x * 256 + threadIdx.x;   // float4 id, [0, 2097152)
    if (gid < 3 * HH)
        bqkv[gid] = gid < HH ? bq[gid] : (gid < 2 * HH ? bk[gid - HH] : bv[gid - 2 * HH]);

    const float* src;
    __nv_bfloat16* dst;
    if (gid < 1048576) {
        src = hidden + (size_t)gid * 4; dst = Hb + (size_t)gid * 4;
    } else if (gid < 1835008) {
        int o = gid - 1048576;          // [0, 786432) float4 within Wqkv
        src = (o < 262144) ? Wq + (size_t)o * 4
            : (o < 524288) ? Wk + (size_t)(o - 262144) * 4
                           : Wv + (size_t)(o - 524288) * 4;
        dst = Wqkv + (size_t)o * 4;
    } else {
        int o = gid - 1835008;
        src = Wd + (size_t)o * 4; dst = Wdb + (size_t)o * 4;
    }
    float4 v = *(const float4*)src;
    *(uint2*)dst = make_uint2(packbf(v.x, v.y), packbf(v.z, v.w));
}

// ---------------------------------------------------------------------------
// Tensor-core GEMM, all-bf16 operands, cp.async 3-stage pipeline.
// out[m,n] = sum_k A[m,k]*W[n,k] + bias[n]
// OMODE 0: N=3072 fused QKV -> bf16 scatter to [b,h,s,d] (Q/K/V by n>>10).
// OMODE 1: N=1024 dense -> fp32 linear + residual.
// Block tile 128x128x32, 8 warps (2M x 4N), warp tile 64x32.
// Dynamic smem: 3 stages x (A 128x40 + B 128x40) bf16 = 61440 B.
// ---------------------------------------------------------------------------
template<int OMODE>
__global__ void __launch_bounds__(256) gemm_async(
    const __nv_bfloat16* __restrict__ A,
    const __nv_bfloat16* __restrict__ Wb,
    const float* __restrict__ bias,
    const float* __restrict__ resid,
    __nv_bfloat16* __restrict__ Qp, __nv_bfloat16* __restrict__ Kp,
    __nv_bfloat16* __restrict__ Vp, float* __restrict__ Xp)
{
    extern __shared__ __nv_bfloat16 smdyn[];
    const int K = 1024;
    const int tid = threadIdx.x, lane = tid & 31, warp = tid >> 5;
    const int wm = warp & 1, wn = warp >> 1;
    const int bm = blockIdx.y * 128, bn = blockIdx.x * 128;
    const unsigned smbase = smem_u32(smdyn);

    float acc[4][4][4];
#pragma unroll
    for (int i = 0; i < 4; i++)
#pragma unroll
        for (int j = 0; j < 4; j++)
#pragma unroll
            for (int k = 0; k < 4; k++) acc[i][j][k] = 0.f;

    const int lr = tid >> 2;            // 0..63
    const int lg = (tid & 3) * 8;       // halfs within 32-k chunk
    auto load_tile = [&](int kt, int stg) {
        unsigned sA = smbase + (unsigned)stg * 20480u;
        unsigned sB = sA + 10240u;
        const __nv_bfloat16* Ab = A  + (size_t)(bm) * K + kt * 32 + lg;
        const __nv_bfloat16* Bb = Wb + (size_t)(bn) * K + kt * 32 + lg;
        CP_ASYNC16(sA + (unsigned)(lr * 40 + lg) * 2u,        Ab + (size_t)lr * K);
        CP_ASYNC16(sA + (unsigned)((lr + 64) * 40 + lg) * 2u, Ab + (size_t)(lr + 64) * K);
        CP_ASYNC16(sB + (unsigned)(lr * 40 + lg) * 2u,        Bb + (size_t)lr * K);
        CP_ASYNC16(sB + (unsigned)((lr + 64) * 40 + lg) * 2u, Bb + (size_t)(lr + 64) * K);
    };

    load_tile(0, 0); CP_COMMIT();
    load_tile(1, 1); CP_COMMIT();

    int s0 = 0;
    for (int t = 0; t < 32; t++) {
        CP_WAIT1();
        __syncthreads();
        int snext = s0 + 2; if (snext >= 3) snext -= 3;
        if (t + 2 < 32) load_tile(t + 2, snext);
        CP_COMMIT();

        unsigned smA = smbase + (unsigned)s0 * 20480u;
        unsigned smB = smA + 10240u;
#pragma unroll
        for (int kk = 0; kk < 2; kk++) {
            unsigned a[4][4], b[4][2];
#pragma unroll
            for (int mt = 0; mt < 4; mt++) {
                int row = wm * 64 + mt * 16 + (lane & 15);
                int col = kk * 16 + (lane >> 4) * 8;
                ldsm4(a[mt], smA + (unsigned)(row * 40 + col) * 2u);
            }
#pragma unroll
            for (int np = 0; np < 2; np++) {
                int row = wn * 32 + np * 16 + (lane & 7) + ((lane >> 4) << 3);
                int col = kk * 16 + ((lane >> 3) & 1) * 8;
                unsigned r[4];
                ldsm4(r, smB + (unsigned)(row * 40 + col) * 2u);
                b[np * 2][0] = r[0];     b[np * 2][1] = r[1];
                b[np * 2 + 1][0] = r[2]; b[np * 2 + 1][1] = r[3];
            }
#pragma unroll
            for (int mt = 0; mt < 4; mt++)
#pragma unroll
                for (int nt = 0; nt < 4; nt++)
                    mma_bf16(acc[mt][nt], a[mt], b[nt]);
        }
        s0 = (s0 + 1 == 3) ? 0 : s0 + 1;
    }

    // Epilogue. c-frag rows: lane>>2 and +8; cols 2*(lane&3)+{0,1}.
#pragma unroll
    for (int mt = 0; mt < 4; mt++) {
        int r0 = bm + wm * 64 + mt * 16 + (lane >> 2);
#pragma unroll
        for (int nt = 0; nt < 4; nt++) {
            int c = bn + wn * 32 + nt * 8 + 2 * (lane & 3);
            float b0 = bias[c], b1 = bias[c + 1];
            float v00 = acc[mt][nt][0] + b0, v01 = acc[mt][nt][1] + b1;
            float v10 = acc[mt][nt][2] + b0, v11 = acc[mt][nt][3] + b1;
            if (OMODE == 0) {
                int which = c >> 10;
                __nv_bfloat16* O = (which == 0) ? Qp : (which == 1) ? Kp : Vp;
                int hc = c & 1023;
                int h = hc >> 6, d = hc & 63;
                {
                    int bi = r0 >> 11, s = r0 & 2047;
                    size_t idx = ((size_t)((bi * NH + h) * SS + s)) * HD + d;
                    *(__nv_bfloat162*)(O + idx) = __floats2bfloat162_rn(v00, v01);
                }
                {
                    int r1 = r0 + 8;
                    int bi = r1 >> 11, s = r1 & 2047;
                    size_t idx = ((size_t)((bi * NH + h) * SS + s)) * HD + d;
                    *(__nv_bfloat162*)(O + idx) = __floats2bfloat162_rn(v10, v11);
                }
            } else {
                size_t i0 = (size_t)r0 * HH + c;
                size_t i1 = (size_t)(r0 + 8) * HH + c;
                *(float2*)(Xp + i0) = make_float2(v00 + resid[i0], v01 + resid[i0 + 1]);
                *(float2*)(Xp + i1) = make_float2(v10 + resid[i1], v11 + resid[i1 + 1]);
            }
        }
    }
}

// ---------------------------------------------------------------------------
// Flash attention, bf16 mma, cp.async 3-stage K/V pipeline (1 barrier/iter).
// Q-tile 128 rows, K-tiles of 64. 8 warps x 16 q-rows, full 64-key width.
// Dyn smem: Q 128x72 + 3x(K 64x72) + 3x(V 64x72) bf16 = 73728 B.
// ---------------------------------------------------------------------------
__global__ void __launch_bounds__(256) flash_mma(
    const __nv_bfloat16* __restrict__ Q,
    const __nv_bfloat16* __restrict__ Kin,
    const __nv_bfloat16* __restrict__ V,
    __nv_bfloat16* __restrict__ Ctx)
{
    extern __shared__ __nv_bfloat16 smf[];
    __nv_bfloat16* Qs = smf;                          // 128*72
    const unsigned smbase = smem_u32(smf);
    const unsigned KOFF = 128 * 72 * 2u;              // bytes
    const unsigned VOFF = KOFF + 3u * 64 * 72 * 2u;
    const unsigned KSTG = 64 * 72 * 2u;               // 9216 B

    const int tid = threadIdx.x, lane = tid & 31, warp = tid >> 5;
    const int bh = blockIdx.y, qt = blockIdx.x;
    const size_t base = (size_t)bh * SS * HD;

    const int lr = tid >> 3;            // 0..31
    const int lg = (tid & 7) * 8;       // halfs within 64-wide row
    auto load_kv = [&](int kt, int stg) {
        unsigned sK = smbase + KOFF + (unsigned)stg * KSTG;
        unsigned sV = smbase + VOFF + (unsigned)stg * KSTG;
        size_t g0 = base + (size_t)(kt * 64 + lr) * HD + lg;
        size_t g1 = base + (size_t)(kt * 64 + lr + 32) * HD + lg;
        CP_ASYNC16(sK + (unsigned)(lr * 72 + lg) * 2u,        Kin + g0);
        CP_ASYNC16(sK + (unsigned)((lr + 32) * 72 + lg) * 2u, Kin + g1);
        CP_ASYNC16(sV + (unsigned)(lr * 72 + lg) * 2u,        V + g0);
        CP_ASYNC16(sV + (unsigned)((lr + 32) * 72 + lg) * 2u, V + g1);
    };

    load_kv(0, 0); CP_COMMIT();
    load_kv(1, 1); CP_COMMIT();

    // Stage Q tile (128 x 64 bf16)
    {
        int row = tid >> 1, seg = (tid & 1) * 32;
        const uint4* s = (const uint4*)(Q + base + (size_t)(qt * 128 + row) * HD + seg);
        uint4* d = (uint4*)(Qs + row * 72 + seg);
        d[0] = s[0]; d[1] = s[1]; d[2] = s[2]; d[3] = s[3];
    }
    __syncthreads();

    // Hoist Q fragments (resident for whole kernel)
    unsigned qa[4][4];
    {
        int row = warp * 16 + (lane & 15);
#pragma unroll
        for (int ks = 0; ks < 4; ks++) {
            int col = ks * 16 + (lane >> 4) * 8;
            ldsm4(qa[ks], smbase + (unsigned)(row * 72 + col) * 2u);
        }
    }

    float ctx[8][4];
#pragma unroll
    for (int o = 0; o < 8; o++)
#pragma unroll
        for (int j = 0; j < 4; j++) ctx[o][j] = 0.f;
    float m0 = -1e30f, m1 = -1e30f, l0 = 0.f, l1 = 0.f;
    const float C = 0.18033688011112042f;   // log2(e)/sqrt(64)

    int s0 = 0;
    for (int kt = 0; kt < SS / 64; kt++) {
        CP_WAIT1();
        __syncthreads();
        int snext = s0 + 2; if (snext >= 3) snext -= 3;
        if (kt + 2 < SS / 64) load_kv(kt + 2, snext);
        CP_COMMIT();

        unsigned smK = smbase + KOFF + (unsigned)s0 * KSTG;
        unsigned smV = smbase + VOFF + (unsigned)s0 * KSTG;

        // S = Q K^T (raw; scale folded into exp)
        float s[8][4];
#pragma unroll
        for (int o = 0; o < 8; o++)
#pragma unroll
            for (int j = 0; j < 4; j++) s[o][j] = 0.f;
#pragma unroll
        for (int ks = 0; ks < 4; ks++) {
            unsigned kb[8][2];
#pragma unroll
            for (int np = 0; np < 4; np++) {
                int row = np * 16 + (lane & 7) + ((lane >> 4) << 3);
                int col = ks * 16 + ((lane >> 3) & 1) * 8;
                unsigned r[4];
                ldsm4(r, smK + (unsigned)(row * 72 + col) * 2u);
                kb[np * 2][0] = r[0];     kb[np * 2][1] = r[1];
                kb[np * 2 + 1][0] = r[2]; kb[np * 2 + 1][1] = r[3];
            }
#pragma unroll
            for (int o = 0; o < 8; o++)
                mma_bf16(s[o], qa[ks], kb[o]);
        }

        // Online softmax (rows lane>>2 and +8; quad shuffles)
        float mx0 = s[0][0], mx1 = s[0][2];
#pragma unroll
        for (int o = 0; o < 8; o++) {
            mx0 = fmaxf(mx0, fmaxf(s[o][0], s[o][1]));
            mx1 = fmaxf(mx1, fmaxf(s[o][2], s[o][3]));
        }
        mx0 = fmaxf(mx0, __shfl_xor_sync(0xffffffffu, mx0, 1));
        mx0 = fmaxf(mx0, __shfl_xor_sync(0xffffffffu, mx0, 2));
        mx1 = fmaxf(mx1, __shfl_xor_sync(0xffffffffu, mx1, 1));
        mx1 = fmaxf(mx1, __shfl_xor_sync(0xffffffffu, mx1, 2));
        float mn0 = fmaxf(m0, mx0), mn1 = fmaxf(m1, mx1);
        float a0 = exp2f((m0 - mn0) * C), a1 = exp2f((m1 - mn1) * C);
        float sum0 = 0.f, sum1 = 0.f;
#pragma unroll
        for (int o = 0; o < 8; o++) {
            s[o][0] = exp2f((s[o][0] - mn0) * C);
            s[o][1] = exp2f((s[o][1] - mn0) * C);
            s[o][2] = exp2f((s[o][2] - mn1) * C);
            s[o][3] = exp2f((s[o][3] - mn1) * C);
            sum0 += s[o][0] + s[o][1];
            sum1 += s[o][2] + s[o][3];
        }
        sum0 += __shfl_xor_sync(0xffffffffu, sum0, 1);
        sum0 += __shfl_xor_sync(0xffffffffu, sum0, 2);
        sum1 += __shfl_xor_sync(0xffffffffu, sum1, 1);
        sum1 += __shfl_xor_sync(0xffffffffu, sum1, 2);
        l0 = l0 * a0 + sum0; l1 = l1 * a1 + sum1;
        m0 = mn0; m1 = mn1;
#pragma unroll
        for (int o = 0; o < 8; o++) {
            ctx[o][0] *= a0; ctx[o][1] *= a0;
            ctx[o][2] *= a1; ctx[o][3] *= a1;
        }

        // ctx += P @ V  (P from score frags; V via ldmatrix.trans)
#pragma unroll
        for (int ks = 0; ks < 4; ks++) {
            unsigned pa[4] = {
                packbf(s[2 * ks][0],     s[2 * ks][1]),
                packbf(s[2 * ks][2],     s[2 * ks][3]),
                packbf(s[2 * ks + 1][0], s[2 * ks + 1][1]),
                packbf(s[2 * ks + 1][2], s[2 * ks + 1][3])
            };
            unsigned vb[8][2];
#pragma unroll
            for (int dp = 0; dp < 4; dp++) {
                int row = ks * 16 + (lane & 7) + (((lane >> 3) & 1) << 3);
                int col = (dp * 2 + (lane >> 4)) * 8;
                unsigned r[4];
                ldsm4t(r, smV + (unsigned)(row * 72 + col) * 2u);
                vb[dp * 2][0] = r[0];     vb[dp * 2][1] = r[1];
                vb[dp * 2 + 1][0] = r[2]; vb[dp * 2 + 1][1] = r[3];
            }
#pragma unroll
            for (int o = 0; o < 8; o++)
                mma_bf16(ctx[o], pa, vb[o]);
        }
        s0 = (s0 + 1 == 3) ? 0 : s0 + 1;
    }

    // Epilogue: normalize, write ctx bf16 in [b, s, h*64+d]
    float inv0 = 1.f / l0, inv1 = 1.f / l1;
    int b = bh >> 4, h = bh & 15;
    int r0 = qt * 128 + warp * 16 + (lane >> 2);
    int r1 = r0 + 8;
#pragma unroll
    for (int o = 0; o < 8; o++) {
        int d = o * 8 + 2 * (lane & 3);
        size_t i0 = ((size_t)(b * SS + r0)) * HH + h * HD + d;
        size_t i1 = ((size_t)(b * SS + r1)) * HH + h * HD + d;
        *(__nv_bfloat162*)(Ctx + i0) = __floats2bfloat162_rn(ctx[o][0] * inv0, ctx[o][1] * inv0);
        *(__nv_bfloat162*)(Ctx + i1) = __floats2bfloat162_rn(ctx[o][2] * inv1, ctx[o][3] * inv1);
    }
}

// ---------------------------------------------------------------------------
// LayerNorm, single-pass (sum + sumsq), one 256-thread block per row.
// ---------------------------------------------------------------------------
__device__ __forceinline__ float2 block_sum2(float2 v) {
    __shared__ float2 red[8];
#pragma unroll
    for (int o = 16; o >= 1; o >>= 1) {
        v.x += __shfl_xor_sync(0xffffffffu, v.x, o);
        v.y += __shfl_xor_sync(0xffffffffu, v.y, o);
    }
    int w = threadIdx.x >> 5;
    if ((threadIdx.x & 31) == 0) red[w] = v;
    __syncthreads();
    if (w == 0) {
        float2 t = (threadIdx.x < 8) ? red[threadIdx.x] : make_float2(0.f, 0.f);
#pragma unroll
        for (int o = 4; o >= 1; o >>= 1) {
            t.x += __shfl_xor_sync(0xffffffffu, t.x, o);
            t.y += __shfl_xor_sync(0xffffffffu, t.y, o);
        }
        if (threadIdx.x == 0) red[0] = t;
    }
    __syncthreads();
    return red[0];
}

__global__ void __launch_bounds__(256) ln_kernel(
    const float* __restrict__ X,
    const float* __restrict__ gamma,
    const float* __restrict__ beta,
    float* __restrict__ out)
{
    const int row = blockIdx.x;
    const int tid = threadIdx.x;
    const float* x = X + (size_t)row * HH;

    float4 v = *(const float4*)&x[tid * 4];
    float2 sp = make_float2(v.x + v.y + v.z + v.w,
                            v.x * v.x + v.y * v.y + v.z * v.z + v.w * v.w);
    float2 t = block_sum2(sp);
    float mean = t.x * (1.f / HH);
    float var = t.y * (1.f / HH) - mean * mean;
    float inv = rsqrtf(var + 1e-5f);

    float4 g  = *(const float4*)&gamma[tid * 4];
    float4 bt = *(const float4*)&beta[tid * 4];
    float4 o;
    o.x = (v.x - mean) * inv * g.x + bt.x;
    o.y = (v.y - mean) * inv * g.y + bt.y;
    o.z = (v.z - mean) * inv * g.z + bt.z;
    o.w = (v.w - mean) * inv * g.w + bt.w;
    *(float4*)&out[(size_t)row * HH + tid * 4] = o;
}

// ---------------------------------------------------------------------------
extern "C" void kernel_launch(void* const* d_in, const int* in_sizes, int n_in,
                              void* d_out, int out_size)
{
    const float* hidden = (const float*)d_in[0];
    const float* Wq = (const float*)d_in[1];  const float* bq = (const float*)d_in[2];
    const float* Wk = (const float*)d_in[3];  const float* bk = (const float*)d_in[4];
    const float* Wv = (const float*)d_in[5];  const float* bv = (const float*)d_in[6];
    const float* Wd = (const float*)d_in[7];  const float* bd = (const float*)d_in[8];
    const float* gamma = (const float*)d_in[9];
    const float* beta  = (const float*)d_in[10];
    float* out = (float*)d_out;

    __nv_bfloat16 *Hb, *Wqkv, *Wdb, *Qp, *Kp, *Vp, *Cp;
    float *bqkv, *Xp;
    cudaGetSymbolAddress((void**)&Hb, g_Hb);
    cudaGetSymbolAddress((void**)&Wqkv, g_Wqkv);
    cudaGetSymbolAddress((void**)&Wdb, g_Wdb);
    cudaGetSymbolAddress((void**)&bqkv, g_bqkv);
    cudaGetSymbolAddress((void**)&Qp, g_Qb);
    cudaGetSymbolAddress((void**)&Kp, g_Kb);
    cudaGetSymbolAddress((void**)&Vp, g_Vb);
    cudaGetSymbolAddress((void**)&Cp, g_Cb);
    cudaGetSymbolAddress((void**)&Xp, g_X);

    const int gemm_smem  = 3 * 2 * 128 * 40 * 2;   // 61440 B
    const int flash_smem = (128 * 72 + 6 * 64 * 72) * 2;  // 73728 B
    cudaFuncSetAttribute(gemm_async<0>,
        cudaFuncAttributeMaxDynamicSharedMemorySize, gemm_smem);
    cudaFuncSetAttribute(gemm_async<1>,
        cudaFuncAttributeMaxDynamicSharedMemorySize, gemm_smem);
    cudaFuncSetAttribute(flash_mma,
        cudaFuncAttributeMaxDynamicSharedMemorySize, flash_smem);

    convert_kernel<<<8192, 256>>>(hidden, Wq, Wk, Wv, Wd, bq, bk, bv,
                                  Hb, Wqkv, Wdb, bqkv);

    // Fused QKV: N = 3072
    gemm_async<0><<<dim3(24, 32), 256, gemm_smem>>>(
        Hb, Wqkv, bqkv, nullptr, Qp, Kp, Vp, nullptr);

    flash_mma<<<dim3(SS / 128, BB * NH), 256, flash_smem>>>(Qp, Kp, Vp, Cp);

    // Dense + residual: N = 1024
    gemm_async<1><<<dim3(8, 32), 256, gemm_smem>>>(
        Cp, Wdb, bd, hidden, nullptr, nullptr, nullptr, Xp);

    ln_kernel<<<MM, 256>>>(Xp, gamma, beta, out);
}

// round 13
// speedup vs baseline: 6.5474x; 1.0062x over previous
#include <cuda_runtime.h>
#include <cuda_bf16.h>
#include <math.h>

// Problem constants
#define BB   2
#define SS   2048
#define HH   1024
#define NH   16
#define HD   64
#define MM   (BB*SS)      // 4096
#define TOT  (MM*HH)      // 4194304

// Scratch (allocation-free rule: __device__ globals)
__device__ __nv_bfloat16 g_Hb[TOT];            // hidden in bf16
__device__ __nv_bfloat16 g_Wqkv[3 * HH * HH];  // packed Wq|Wk|Wv bf16
__device__ __nv_bfloat16 g_Wdb[HH * HH];       // Wd bf16
__device__ float         g_bqkv[3 * HH];       // packed bias
__device__ __nv_bfloat16 g_Qb[TOT];
__device__ __nv_bfloat16 g_Kb[TOT];
__device__ __nv_bfloat16 g_Vb[TOT];
__device__ __nv_bfloat16 g_Cb[TOT];
__device__ float g_X[TOT];

// ---------------------------------------------------------------------------
// Helpers
// ---------------------------------------------------------------------------
__device__ __forceinline__ unsigned smem_u32(const void* p) {
    return (unsigned)__cvta_generic_to_shared(p);
}
__device__ __forceinline__ void ldsm4(unsigned* r, unsigned a) {
    asm volatile("ldmatrix.sync.aligned.m8n8.x4.shared.b16 {%0,%1,%2,%3}, [%4];"
        : "=r"(r[0]), "=r"(r[1]), "=r"(r[2]), "=r"(r[3]) : "r"(a));
}
__device__ __forceinline__ void ldsm4t(unsigned* r, unsigned a) {
    asm volatile("ldmatrix.sync.aligned.m8n8.x4.trans.shared.b16 {%0,%1,%2,%3}, [%4];"
        : "=r"(r[0]), "=r"(r[1]), "=r"(r[2]), "=r"(r[3]) : "r"(a));
}
__device__ __forceinline__ void mma_bf16(float* c, const unsigned* a, const unsigned* b) {
    asm volatile(
        "mma.sync.aligned.m16n8k16.row.col.f32.bf16.bf16.f32 "
        "{%0,%1,%2,%3}, {%4,%5,%6,%7}, {%8,%9}, {%0,%1,%2,%3};"
        : "+f"(c[0]), "+f"(c[1]), "+f"(c[2]), "+f"(c[3])
        : "r"(a[0]), "r"(a[1]), "r"(a[2]), "r"(a[3]), "r"(b[0]), "r"(b[1]));
}
__device__ __forceinline__ unsigned packbf(float lo, float hi) {
    unsigned d;
    asm("cvt.rn.bf16x2.f32 %0, %1, %2;" : "=r"(d) : "f"(hi), "f"(lo));
    return d;
}
#define CP_ASYNC16(dst, src) \
    asm volatile("cp.async.cg.shared.global [%0], [%1], 16;" :: "r"(dst), "l"(src))
#define CP_COMMIT()  asm volatile("cp.async.commit_group;")
#define CP_WAIT1()   asm volatile("cp.async.wait_group 1;")

// ---------------------------------------------------------------------------
// Convert/pack pass: hidden -> bf16, Wq|Wk|Wv -> packed bf16, Wd -> bf16,
// bq|bk|bv -> packed fp32. One float4 per thread, grid 8192 x 256.
// ---------------------------------------------------------------------------
__global__ void __launch_bounds__(256) convert_kernel(
    const float* __restrict__ hidden,
    const float* __restrict__ Wq, const float* __restrict__ Wk,
    const float* __restrict__ Wv, const float* __restrict__ Wd,
    const float* __restrict__ bq, const float* __restrict__ bk,
    const float* __restrict__ bv,
    __nv_bfloat16* __restrict__ Hb, __nv_bfloat16* __restrict__ Wqkv,
    __nv_bfloat16* __restrict__ Wdb, float* __restrict__ bqkv)
{
    int gid = blockIdx.x * 256 + threadIdx.x;   // float4 id, [0, 2097152)
    if (gid < 3 * HH)
        bqkv[gid] = gid < HH ? bq[gid] : (gid < 2 * HH ? bk[gid - HH] : bv[gid - 2 * HH]);

    const float* src;
    __nv_bfloat16* dst;
    if (gid < 1048576) {
        src = hidden + (size_t)gid * 4; dst = Hb + (size_t)gid * 4;
    } else if (gid < 1835008) {
        int o = gid - 1048576;          // [0, 786432) float4 within Wqkv
        src = (o < 262144) ? Wq + (size_t)o * 4
            : (o < 524288) ? Wk + (size_t)(o - 262144) * 4
                           : Wv + (size_t)(o - 524288) * 4;
        dst = Wqkv + (size_t)o * 4;
    } else {
        int o = gid - 1835008;
        src = Wd + (size_t)o * 4; dst = Wdb + (size_t)o * 4;
    }
    float4 v = *(const float4*)src;
    *(uint2*)dst = make_uint2(packbf(v.x, v.y), packbf(v.z, v.w));
}

// ---------------------------------------------------------------------------
// Tensor-core GEMM, all-bf16 operands, cp.async 3-stage pipeline, K-chunk 64.
// out[m,n] = sum_k A[m,k]*W[n,k] + bias[n]
// OMODE 0: N=3072 fused QKV -> bf16 scatter to [b,h,s,d] (Q/K/V by n>>10).
// OMODE 1: N=1024 dense -> fp32 linear + residual.
// Block tile 128x128x64, 8 warps (2M x 4N), warp tile 64x32.
// Dyn smem: 3 stages x (A 128x72 + B 128x72) bf16 = 110592 B.
// ---------------------------------------------------------------------------
template<int OMODE>
__global__ void __launch_bounds__(256) gemm_async(
    const __nv_bfloat16* __restrict__ A,
    const __nv_bfloat16* __restrict__ Wb,
    const float* __restrict__ bias,
    const float* __restrict__ resid,
    __nv_bfloat16* __restrict__ Qp, __nv_bfloat16* __restrict__ Kp,
    __nv_bfloat16* __restrict__ Vp, float* __restrict__ Xp)
{
    extern __shared__ __nv_bfloat16 smdyn[];
    const int K = 1024;
    const int tid = threadIdx.x, lane = tid & 31, warp = tid >> 5;
    const int wm = warp & 1, wn = warp >> 1;
    const int bm = blockIdx.y * 128, bn = blockIdx.x * 128;
    const unsigned smbase = smem_u32(smdyn);
    const unsigned STG = 2u * 128 * 72 * 2;   // 36864 B per stage (A+B)
    const unsigned BOFF = 128 * 72 * 2;       // 18432 B

    float acc[4][4][4];
#pragma unroll
    for (int i = 0; i < 4; i++)
#pragma unroll
        for (int j = 0; j < 4; j++)
#pragma unroll
            for (int k = 0; k < 4; k++) acc[i][j][k] = 0.f;

    const int lr = tid >> 2;            // 0..63
    const int lg = (tid & 3) * 16;      // halfs within 64-k chunk
    auto load_tile = [&](int kt, int stg) {
        unsigned sA = smbase + (unsigned)stg * STG;
        unsigned sB = sA + BOFF;
        const __nv_bfloat16* Ab = A  + (size_t)bm * K + kt * 64 + lg;
        const __nv_bfloat16* Bb = Wb + (size_t)bn * K + kt * 64 + lg;
#pragma unroll
        for (int h = 0; h < 2; h++) {
            int row = lr + h * 64;
            unsigned da = sA + (unsigned)(row * 72 + lg) * 2u;
            unsigned db = sB + (unsigned)(row * 72 + lg) * 2u;
            CP_ASYNC16(da,       Ab + (size_t)row * K);
            CP_ASYNC16(da + 16u, Ab + (size_t)row * K + 8);
            CP_ASYNC16(db,       Bb + (size_t)row * K);
            CP_ASYNC16(db + 16u, Bb + (size_t)row * K + 8);
        }
    };

    load_tile(0, 0); CP_COMMIT();
    load_tile(1, 1); CP_COMMIT();

    int s0 = 0;
    for (int t = 0; t < 16; t++) {
        CP_WAIT1();
        __syncthreads();
        int snext = s0 + 2; if (snext >= 3) snext -= 3;
        if (t + 2 < 16) load_tile(t + 2, snext);
        CP_COMMIT();

        unsigned smA = smbase + (unsigned)s0 * STG;
        unsigned smB = smA + BOFF;
#pragma unroll
        for (int kk = 0; kk < 4; kk++) {
            unsigned a[4][4], b[4][2];
#pragma unroll
            for (int mt = 0; mt < 4; mt++) {
                int row = wm * 64 + mt * 16 + (lane & 15);
                int col = kk * 16 + (lane >> 4) * 8;
                ldsm4(a[mt], smA + (unsigned)(row * 72 + col) * 2u);
            }
#pragma unroll
            for (int np = 0; np < 2; np++) {
                int row = wn * 32 + np * 16 + (lane & 7) + ((lane >> 4) << 3);
                int col = kk * 16 + ((lane >> 3) & 1) * 8;
                unsigned r[4];
                ldsm4(r, smB + (unsigned)(row * 72 + col) * 2u);
                b[np * 2][0] = r[0];     b[np * 2][1] = r[1];
                b[np * 2 + 1][0] = r[2]; b[np * 2 + 1][1] = r[3];
            }
#pragma unroll
            for (int mt = 0; mt < 4; mt++)
#pragma unroll
                for (int nt = 0; nt < 4; nt++)
                    mma_bf16(acc[mt][nt], a[mt], b[nt]);
        }
        s0 = (s0 + 1 == 3) ? 0 : s0 + 1;
    }

    // Epilogue. c-frag rows: lane>>2 and +8; cols 2*(lane&3)+{0,1}.
#pragma unroll
    for (int mt = 0; mt < 4; mt++) {
        int r0 = bm + wm * 64 + mt * 16 + (lane >> 2);
#pragma unroll
        for (int nt = 0; nt < 4; nt++) {
            int c = bn + wn * 32 + nt * 8 + 2 * (lane & 3);
            float b0 = bias[c], b1 = bias[c + 1];
            float v00 = acc[mt][nt][0] + b0, v01 = acc[mt][nt][1] + b1;
            float v10 = acc[mt][nt][2] + b0, v11 = acc[mt][nt][3] + b1;
            if (OMODE == 0) {
                int which = c >> 10;
                __nv_bfloat16* O = (which == 0) ? Qp : (which == 1) ? Kp : Vp;
                int hc = c & 1023;
                int h = hc >> 6, d = hc & 63;
                {
                    int bi = r0 >> 11, s = r0 & 2047;
                    size_t idx = ((size_t)((bi * NH + h) * SS + s)) * HD + d;
                    *(__nv_bfloat162*)(O + idx) = __floats2bfloat162_rn(v00, v01);
                }
                {
                    int r1 = r0 + 8;
                    int bi = r1 >> 11, s = r1 & 2047;
                    size_t idx = ((size_t)((bi * NH + h) * SS + s)) * HD + d;
                    *(__nv_bfloat162*)(O + idx) = __floats2bfloat162_rn(v10, v11);
                }
            } else {
                size_t i0 = (size_t)r0 * HH + c;
                size_t i1 = (size_t)(r0 + 8) * HH + c;
                *(float2*)(Xp + i0) = make_float2(v00 + resid[i0], v01 + resid[i0 + 1]);
                *(float2*)(Xp + i1) = make_float2(v10 + resid[i1], v11 + resid[i1 + 1]);
            }
        }
    }
}

// ---------------------------------------------------------------------------
// Flash attention, bf16 mma, cp.async 3-stage K/V pipeline.
// 128 threads = 4 warps; q-tile 128 rows, 32 q-rows per warp (2 m-frags),
// K-tiles of 64. K/V fragments amortized over 2x the q-rows vs R8.
// Dyn smem: Q 128x72 + 3x(K 64x72) + 3x(V 64x72) bf16 = 73728 B.
// ---------------------------------------------------------------------------
__global__ void __launch_bounds__(128, 2) flash_mma(
    const __nv_bfloat16* __restrict__ Q,
    const __nv_bfloat16* __restrict__ Kin,
    const __nv_bfloat16* __restrict__ V,
    __nv_bfloat16* __restrict__ Ctx)
{
    extern __shared__ __nv_bfloat16 smf[];
    __nv_bfloat16* Qs = smf;                          // 128*72
    const unsigned smbase = smem_u32(smf);
    const unsigned KOFF = 128 * 72 * 2u;              // bytes
    const unsigned VOFF = KOFF + 3u * 64 * 72 * 2u;
    const unsigned KSTG = 64 * 72 * 2u;               // 9216 B

    const int tid = threadIdx.x, lane = tid & 31, warp = tid >> 5;  // warp 0..3
    const int bh = blockIdx.y, qt = blockIdx.x;
    const size_t base = (size_t)bh * SS * HD;

    const int lr = tid >> 1;            // 0..63
    const int lg = (tid & 1) * 32;      // halfs within 64-wide row
    auto load_kv = [&](int kt, int stg) {
        unsigned sK = smbase + KOFF + (unsigned)stg * KSTG;
        unsigned sV = smbase + VOFF + (unsigned)stg * KSTG;
        size_t g = base + (size_t)(kt * 64 + lr) * HD + lg;
        unsigned dk = sK + (unsigned)(lr * 72 + lg) * 2u;
        unsigned dv = sV + (unsigned)(lr * 72 + lg) * 2u;
#pragma unroll
        for (int i = 0; i < 4; i++) {
            CP_ASYNC16(dk + i * 16u, Kin + g + i * 8);
            CP_ASYNC16(dv + i * 16u, V + g + i * 8);
        }
    };

    load_kv(0, 0); CP_COMMIT();
    load_kv(1, 1); CP_COMMIT();

    // Stage Q tile (128 x 64 bf16): one FULL row (8 x uint4 = 128 B) per thread
    {
        const uint4* s = (const uint4*)(Q + base + (size_t)(qt * 128 + tid) * HD);
        uint4* d = (uint4*)(Qs + tid * 72);
#pragma unroll
        for (int i = 0; i < 8; i++) d[i] = s[i];
    }
    __syncthreads();

    // Hoist Q fragments: 2 m-tiles x 4 k-steps (resident whole kernel)
    unsigned qa[2][4][4];
#pragma unroll
    for (int mt = 0; mt < 2; mt++) {
        int row = warp * 32 + mt * 16 + (lane & 15);
#pragma unroll
        for (int ks = 0; ks < 4; ks++) {
            int col = ks * 16 + (lane >> 4) * 8;
            ldsm4(qa[mt][ks], smbase + (unsigned)(row * 72 + col) * 2u);
        }
    }

    float ctx[2][8][4];
#pragma unroll
    for (int mt = 0; mt < 2; mt++)
#pragma unroll
        for (int o = 0; o < 8; o++)
#pragma unroll
            for (int j = 0; j < 4; j++) ctx[mt][o][j] = 0.f;
    float mI[2][2], lI[2][2];
#pragma unroll
    for (int mt = 0; mt < 2; mt++) {
        mI[mt][0] = mI[mt][1] = -1e30f;
        lI[mt][0] = lI[mt][1] = 0.f;
    }
    const float C = 0.18033688011112042f;   // log2(e)/sqrt(64)

    int s0 = 0;
    for (int kt = 0; kt < SS / 64; kt++) {
        CP_WAIT1();
        __syncthreads();
        int snext = s0 + 2; if (snext >= 3) snext -= 3;
        if (kt + 2 < SS / 64) load_kv(kt + 2, snext);
        CP_COMMIT();

        unsigned smK = smbase + KOFF + (unsigned)s0 * KSTG;
        unsigned smV = smbase + VOFF + (unsigned)s0 * KSTG;

        // S = Q K^T (raw; scale folded into exp)
        float s[2][8][4];
#pragma unroll
        for (int mt = 0; mt < 2; mt++)
#pragma unroll
            for (int o = 0; o < 8; o++)
#pragma unroll
                for (int j = 0; j < 4; j++) s[mt][o][j] = 0.f;
#pragma unroll
        for (int ks = 0; ks < 4; ks++) {
            unsigned kb[8][2];
#pragma unroll
            for (int np = 0; np < 4; np++) {
                int row = np * 16 + (lane & 7) + ((lane >> 4) << 3);
                int col = ks * 16 + ((lane >> 3) & 1) * 8;
                unsigned r[4];
                ldsm4(r, smK + (unsigned)(row * 72 + col) * 2u);
                kb[np * 2][0] = r[0];     kb[np * 2][1] = r[1];
                kb[np * 2 + 1][0] = r[2]; kb[np * 2 + 1][1] = r[3];
            }
#pragma unroll
            for (int mt = 0; mt < 2; mt++)
#pragma unroll
                for (int o = 0; o < 8; o++)
                    mma_bf16(s[mt][o], qa[mt][ks], kb[o]);
        }

        // Online softmax per m-tile (rows lane>>2 and +8; quad shuffles)
        float alpha[2][2];
#pragma unroll
        for (int mt = 0; mt < 2; mt++) {
            float mx0 = s[mt][0][0], mx1 = s[mt][0][2];
#pragma unroll
            for (int o = 0; o < 8; o++) {
                mx0 = fmaxf(mx0, fmaxf(s[mt][o][0], s[mt][o][1]));
                mx1 = fmaxf(mx1, fmaxf(s[mt][o][2], s[mt][o][3]));
            }
            mx0 = fmaxf(mx0, __shfl_xor_sync(0xffffffffu, mx0, 1));
            mx0 = fmaxf(mx0, __shfl_xor_sync(0xffffffffu, mx0, 2));
            mx1 = fmaxf(mx1, __shfl_xor_sync(0xffffffffu, mx1, 1));
            mx1 = fmaxf(mx1, __shfl_xor_sync(0xffffffffu, mx1, 2));
            float mn0 = fmaxf(mI[mt][0], mx0), mn1 = fmaxf(mI[mt][1], mx1);
            alpha[mt][0] = exp2f((mI[mt][0] - mn0) * C);
            alpha[mt][1] = exp2f((mI[mt][1] - mn1) * C);
            float sum0 = 0.f, sum1 = 0.f;
#pragma unroll
            for (int o = 0; o < 8; o++) {
                s[mt][o][0] = exp2f((s[mt][o][0] - mn0) * C);
                s[mt][o][1] = exp2f((s[mt][o][1] - mn0) * C);
                s[mt][o][2] = exp2f((s[mt][o][2] - mn1) * C);
                s[mt][o][3] = exp2f((s[mt][o][3] - mn1) * C);
                sum0 += s[mt][o][0] + s[mt][o][1];
                sum1 += s[mt][o][2] + s[mt][o][3];
            }
            sum0 += __shfl_xor_sync(0xffffffffu, sum0, 1);
            sum0 += __shfl_xor_sync(0xffffffffu, sum0, 2);
            sum1 += __shfl_xor_sync(0xffffffffu, sum1, 1);
            sum1 += __shfl_xor_sync(0xffffffffu, sum1, 2);
            lI[mt][0] = lI[mt][0] * alpha[mt][0] + sum0;
            lI[mt][1] = lI[mt][1] * alpha[mt][1] + sum1;
            mI[mt][0] = mn0; mI[mt][1] = mn1;
#pragma unroll
            for (int o = 0; o < 8; o++) {
                ctx[mt][o][0] *= alpha[mt][0]; ctx[mt][o][1] *= alpha[mt][0];
                ctx[mt][o][2] *= alpha[mt][1]; ctx[mt][o][3] *= alpha[mt][1];
            }
        }

        // ctx += P @ V  (P from score frags; V via ldmatrix.trans)
#pragma unroll
        for (int ks = 0; ks < 4; ks++) {
            unsigned vb[8][2];
#pragma unroll
            for (int dp = 0; dp < 4; dp++) {
                int row = ks * 16 + (lane & 7) + (((lane >> 3) & 1) << 3);
                int col = (dp * 2 + (lane >> 4)) * 8;
                unsigned r[4];
                ldsm4t(r, smV + (unsigned)(row * 72 + col) * 2u);
                vb[dp * 2][0] = r[0];     vb[dp * 2][1] = r[1];
                vb[dp * 2 + 1][0] = r[2]; vb[dp * 2 + 1][1] = r[3];
            }
#pragma unroll
            for (int mt = 0; mt < 2; mt++) {
                unsigned pa[4] = {
                    packbf(s[mt][2 * ks][0],     s[mt][2 * ks][1]),
                    packbf(s[mt][2 * ks][2],     s[mt][2 * ks][3]),
                    packbf(s[mt][2 * ks + 1][0], s[mt][2 * ks + 1][1]),
                    packbf(s[mt][2 * ks + 1][2], s[mt][2 * ks + 1][3])
                };
#pragma unroll
                for (int o = 0; o < 8; o++)
                    mma_bf16(ctx[mt][o], pa, vb[o]);
            }
        }
        s0 = (s0 + 1 == 3) ? 0 : s0 + 1;
    }

    // Epilogue: normalize, write ctx bf16 in [b, s, h*64+d]
    int b = bh >> 4, h = bh & 15;
#pragma unroll
    for (int mt = 0; mt < 2; mt++) {
        float inv0 = 1.f / lI[mt][0], inv1 = 1.f / lI[mt][1];
        int r0 = qt * 128 + warp * 32 + mt * 16 + (lane >> 2);
        int r1 = r0 + 8;
#pragma unroll
        for (int o = 0; o < 8; o++) {
            int d = o * 8 + 2 * (lane & 3);
            size_t i0 = ((size_t)(b * SS + r0)) * HH + h * HD + d;
            size_t i1 = ((size_t)(b * SS + r1)) * HH + h * HD + d;
            *(__nv_bfloat162*)(Ctx + i0) =
                __floats2bfloat162_rn(ctx[mt][o][0] * inv0, ctx[mt][o][1] * inv0);
            *(__nv_bfloat162*)(Ctx + i1) =
                __floats2bfloat162_rn(ctx[mt][o][2] * inv1, ctx[mt][o][3] * inv1);
        }
    }
}

// ---------------------------------------------------------------------------
// LayerNorm, single-pass (sum + sumsq), one 256-thread block per row.
// ---------------------------------------------------------------------------
__device__ __forceinline__ float2 block_sum2(float2 v) {
    __shared__ float2 red[8];
#pragma unroll
    for (int o = 16; o >= 1; o >>= 1) {
        v.x += __shfl_xor_sync(0xffffffffu, v.x, o);
        v.y += __shfl_xor_sync(0xffffffffu, v.y, o);
    }
    int w = threadIdx.x >> 5;
    if ((threadIdx.x & 31) == 0) red[w] = v;
    __syncthreads();
    if (w == 0) {
        float2 t = (threadIdx.x < 8) ? red[threadIdx.x] : make_float2(0.f, 0.f);
#pragma unroll
        for (int o = 4; o >= 1; o >>= 1) {
            t.x += __shfl_xor_sync(0xffffffffu, t.x, o);
            t.y += __shfl_xor_sync(0xffffffffu, t.y, o);
        }
        if (threadIdx.x == 0) red[0] = t;
    }
    __syncthreads();
    return red[0];
}

__global__ void __launch_bounds__(256) ln_kernel(
    const float* __restrict__ X,
    const float* __restrict__ gamma,
    const float* __restrict__ beta,
    float* __restrict__ out)
{
    const int row = blockIdx.x;
    const int tid = threadIdx.x;
    const float* x = X + (size_t)row * HH;

    float4 v = *(const float4*)&x[tid * 4];
    float2 sp = make_float2(v.x + v.y + v.z + v.w,
                            v.x * v.x + v.y * v.y + v.z * v.z + v.w * v.w);
    float2 t = block_sum2(sp);
    float mean = t.x * (1.f / HH);
    float var = t.y * (1.f / HH) - mean * mean;
    float inv = rsqrtf(var + 1e-5f);

    float4 g  = *(const float4*)&gamma[tid * 4];
    float4 bt = *(const float4*)&beta[tid * 4];
    float4 o;
    o.x = (v.x - mean) * inv * g.x + bt.x;
    o.y = (v.y - mean) * inv * g.y + bt.y;
    o.z = (v.z - mean) * inv * g.z + bt.z;
    o.w = (v.w - mean) * inv * g.w + bt.w;
    *(float4*)&out[(size_t)row * HH + tid * 4] = o;
}

// ---------------------------------------------------------------------------
extern "C" void kernel_launch(void* const* d_in, const int* in_sizes, int n_in,
                              void* d_out, int out_size)
{
    const float* hidden = (const float*)d_in[0];
    const float* Wq = (const float*)d_in[1];  const float* bq = (const float*)d_in[2];
    const float* Wk = (const float*)d_in[3];  const float* bk = (const float*)d_in[4];
    const float* Wv = (const float*)d_in[5];  const float* bv = (const float*)d_in[6];
    const float* Wd = (const float*)d_in[7];  const float* bd = (const float*)d_in[8];
    const float* gamma = (const float*)d_in[9];
    const float* beta  = (const float*)d_in[10];
    float* out = (float*)d_out;

    __nv_bfloat16 *Hb, *Wqkv, *Wdb, *Qp, *Kp, *Vp, *Cp;
    float *bqkv, *Xp;
    cudaGetSymbolAddress((void**)&Hb, g_Hb);
    cudaGetSymbolAddress((void**)&Wqkv, g_Wqkv);
    cudaGetSymbolAddress((void**)&Wdb, g_Wdb);
    cudaGetSymbolAddress((void**)&bqkv, g_bqkv);
    cudaGetSymbolAddress((void**)&Qp, g_Qb);
    cudaGetSymbolAddress((void**)&Kp, g_Kb);
    cudaGetSymbolAddress((void**)&Vp, g_Vb);
    cudaGetSymbolAddress((void**)&Cp, g_Cb);
    cudaGetSymbolAddress((void**)&Xp, g_X);

    const int gemm_smem  = 3 * 2 * 128 * 72 * 2;          // 110592 B
    const int flash_smem = (128 * 72 + 6 * 64 * 72) * 2;  // 73728 B
    cudaFuncSetAttribute(gemm_async<0>,
        cudaFuncAttributeMaxDynamicSharedMemorySize, gemm_smem);
    cudaFuncSetAttribute(gemm_async<1>,
        cudaFuncAttributeMaxDynamicSharedMemorySize, gemm_smem);
    cudaFuncSetAttribute(flash_mma,
        cudaFuncAttributeMaxDynamicSharedMemorySize, flash_smem);

    convert_kernel<<<8192, 256>>>(hidden, Wq, Wk, Wv, Wd, bq, bk, bv,
                                  Hb, Wqkv, Wdb, bqkv);

    // Fused QKV: N = 3072
    gemm_async<0><<<dim3(24, 32), 256, gemm_smem>>>(
        Hb, Wqkv, bqkv, nullptr, Qp, Kp, Vp, nullptr);

    flash_mma<<<dim3(SS / 128, BB * NH), 128, flash_smem>>>(Qp, Kp, Vp, Cp);

    // Dense + residual: N = 1024
    gemm_async<1><<<dim3(8, 32), 256, gemm_smem>>>(
        Cp, Wdb, bd, hidden, nullptr, nullptr, nullptr, Xp);

    ln_kernel<<<MM, 256>>>(Xp, gamma, beta, out);
}